// round 1
// baseline (speedup 1.0000x reference)
#include <cuda_runtime.h>
#include <cstdint>

#define S 8192
#define H 1024
#define NSM 128
#define SCAN_THREADS 512

// Scratch: input-side gate projections gx[S][3H] and per-step completion counters.
__device__ float g_gx[(size_t)S * 3 * H];
__device__ unsigned int g_flags[S];

// ---------------------------------------------------------------------------
// Kernel 1: clear per-step flags (graph replays need a fresh counter array)
// ---------------------------------------------------------------------------
__global__ void clear_flags_kernel() {
    int i = blockIdx.x * blockDim.x + threadIdx.x;
    if (i < S) g_flags[i] = 0u;
}

// ---------------------------------------------------------------------------
// Kernel 2: gx = inp @ W_ih^T + b_ih   (fp32 SIMT GEMM, 128x128x16 tiles)
//   A = inp [S][1024], B^T = W_ih [3072][1024], C = g_gx [S][3072]
// ---------------------------------------------------------------------------
__global__ __launch_bounds__(256) void gemm_gx_kernel(
    const float* __restrict__ A,
    const float* __restrict__ Wih,
    const float* __restrict__ bih)
{
    __shared__ float As[16][128 + 4];
    __shared__ float Bs[16][128 + 4];

    const int tid = threadIdx.x;
    const int m0 = blockIdx.y * 128;
    const int n0 = blockIdx.x * 128;
    const int tx = tid & 15;   // 16 thread-cols
    const int ty = tid >> 4;   // 16 thread-rows

    float acc[8][8] = {};

    for (int kt = 0; kt < 1024; kt += 16) {
        // A tile: 128 rows x 16 k -> store transposed As[k][m]
#pragma unroll
        for (int r = 0; r < 2; ++r) {
            int idx = tid + r * 256;
            int row = idx >> 2;
            int kq  = idx & 3;
            float4 v = *(const float4*)(A + (size_t)(m0 + row) * 1024 + kt + kq * 4);
            As[kq * 4 + 0][row] = v.x;
            As[kq * 4 + 1][row] = v.y;
            As[kq * 4 + 2][row] = v.z;
            As[kq * 4 + 3][row] = v.w;
        }
        // B tile: Bs[k][n] = Wih[n0+n][kt+k]
#pragma unroll
        for (int r = 0; r < 2; ++r) {
            int idx = tid + r * 256;
            int n  = idx >> 2;
            int kq = idx & 3;
            float4 v = *(const float4*)(Wih + (size_t)(n0 + n) * 1024 + kt + kq * 4);
            Bs[kq * 4 + 0][n] = v.x;
            Bs[kq * 4 + 1][n] = v.y;
            Bs[kq * 4 + 2][n] = v.z;
            Bs[kq * 4 + 3][n] = v.w;
        }
        __syncthreads();

#pragma unroll
        for (int k = 0; k < 16; ++k) {
            float ra[8], rb[8];
#pragma unroll
            for (int i = 0; i < 8; ++i) ra[i] = As[k][ty * 8 + i];
#pragma unroll
            for (int i = 0; i < 8; ++i) rb[i] = Bs[k][tx * 8 + i];
#pragma unroll
            for (int i = 0; i < 8; ++i)
#pragma unroll
                for (int j = 0; j < 8; ++j)
                    acc[i][j] = fmaf(ra[i], rb[j], acc[i][j]);
        }
        __syncthreads();
    }

    // epilogue: add bias, vectorized float4 stores
#pragma unroll
    for (int i = 0; i < 8; ++i) {
        size_t rowoff = (size_t)(m0 + ty * 8 + i) * 3072 + n0 + tx * 8;
#pragma unroll
        for (int jq = 0; jq < 2; ++jq) {
            float4 v;
            v.x = acc[i][jq * 4 + 0] + bih[n0 + tx * 8 + jq * 4 + 0];
            v.y = acc[i][jq * 4 + 1] + bih[n0 + tx * 8 + jq * 4 + 1];
            v.z = acc[i][jq * 4 + 2] + bih[n0 + tx * 8 + jq * 4 + 2];
            v.w = acc[i][jq * 4 + 3] + bih[n0 + tx * 8 + jq * 4 + 3];
            *(float4*)(g_gx + rowoff + jq * 4) = v;
        }
    }
}

// ---------------------------------------------------------------------------
// Kernel 3: persistent GRU scan. 128 CTAs (one per SM, single wave),
// 512 threads each. Each CTA owns 8 output dims => 24 gate-rows of W_hh,
// held entirely in registers (48 floats/thread). h_t lives in d_out and is
// exchanged through L2; a per-step counter provides release/acquire sync.
//
// Thread layout: 16 warps = 4 k-chunks (256 cols each) x 4 row-groups
// (6 gate-rows each). Lane l owns 8 consecutive k within its chunk.
// ---------------------------------------------------------------------------
__global__ __launch_bounds__(SCAN_THREADS, 1) void gru_scan_kernel(
    const float* __restrict__ Whh,
    const float* __restrict__ bhh,
    float* out)
{
    const int tid  = threadIdx.x;
    const int warp = tid >> 5;
    const int lane = tid & 31;
    const int c = warp & 3;        // k-chunk id (0..3)
    const int g = warp >> 2;       // row-group id (0..3)
    const int bid = blockIdx.x;
    const int obase = bid * 8;     // first output dim owned by this CTA
    const int k0 = c * 256 + lane * 8;

    __shared__ float partials[4][24];   // [k-chunk][gate-row within CTA]

    // --- preload 6 gate-rows x 8 cols of W_hh into registers ---
    float w[6][8];
#pragma unroll
    for (int j = 0; j < 6; ++j) {
        int gr   = g * 6 + j;                       // 0..23
        int row  = (gr >> 3) * H + obase + (gr & 7); // gate*H + output index
        const float4* p = (const float4*)(Whh + (size_t)row * H + k0);
        float4 a = p[0], b = p[1];
        w[j][0] = a.x; w[j][1] = a.y; w[j][2] = a.z; w[j][3] = a.w;
        w[j][4] = b.x; w[j][5] = b.y; w[j][6] = b.z; w[j][7] = b.w;
    }

    // --- finalizer threads: warp 0, lanes 0..7 (one per owned output dim) ---
    const bool fin = (warp == 0 && lane < 8);
    float bh_r = 0.f, bh_z = 0.f, bh_n = 0.f, hprev = 0.f;
    if (fin) {
        bh_r = bhh[0 * H + obase + lane];
        bh_z = bhh[1 * H + obase + lane];
        bh_n = bhh[2 * H + obase + lane];
    }

    volatile unsigned int* vflags = (volatile unsigned int*)g_flags;

    for (int t = 0; t < S; ++t) {
        // prefetch gx for this step (independent of h -> hides L2 latency)
        float gx_r = 0.f, gx_z = 0.f, gx_n = 0.f;
        if (fin) {
            const float* gx = g_gx + (size_t)t * (3 * H) + obase + lane;
            gx_r = gx[0];
            gx_z = gx[H];
            gx_n = gx[2 * H];
        }

        float h[8];
        if (t == 0) {
#pragma unroll
            for (int k = 0; k < 8; ++k) h[k] = 0.f;
        } else {
            // wait for all 128 CTAs to have published h_{t-1}
            while (vflags[t - 1] != (unsigned)NSM) { }
            __threadfence();   // acquire
            const float4* hp = (const float4*)(out + (size_t)(t - 1) * H + k0);
            float4 a = hp[0], b = hp[1];
            h[0] = a.x; h[1] = a.y; h[2] = a.z; h[3] = a.w;
            h[4] = b.x; h[5] = b.y; h[6] = b.z; h[7] = b.w;
        }

        // --- per-thread partial dots: 6 rows x 8 k ---
        float acc[6];
#pragma unroll
        for (int j = 0; j < 6; ++j) {
            float s = 0.f;
#pragma unroll
            for (int k = 0; k < 8; ++k) s = fmaf(w[j][k], h[k], s);
            acc[j] = s;
        }

        // --- intra-warp reduction (sum 32 lanes = 256 k's) ---
#pragma unroll
        for (int j = 0; j < 6; ++j) {
#pragma unroll
            for (int off = 16; off > 0; off >>= 1)
                acc[j] += __shfl_xor_sync(0xFFFFFFFFu, acc[j], off);
        }
        if (lane == 0) {
#pragma unroll
            for (int j = 0; j < 6; ++j) partials[c][g * 6 + j] = acc[j];
        }
        __syncthreads();

        // --- finalize gates for the 8 owned output dims ---
        if (fin) {
            int o = lane;
            float gh_r = bh_r + partials[0][0 * 8 + o] + partials[1][0 * 8 + o]
                              + partials[2][0 * 8 + o] + partials[3][0 * 8 + o];
            float gh_z = bh_z + partials[0][1 * 8 + o] + partials[1][1 * 8 + o]
                              + partials[2][1 * 8 + o] + partials[3][1 * 8 + o];
            float gh_n = bh_n + partials[0][2 * 8 + o] + partials[1][2 * 8 + o]
                              + partials[2][2 * 8 + o] + partials[3][2 * 8 + o];

            float r = 1.f / (1.f + __expf(-(gx_r + gh_r)));
            float z = 1.f / (1.f + __expf(-(gx_z + gh_z)));
            float n = tanhf(gx_n + r * gh_n);
            float hn = z * (hprev - n) + n;   // (1-z)*n + z*h
            hprev = hn;
            out[(size_t)t * H + obase + o] = hn;
        }

        // Publish: full-warp0 syncwarp orders (a) lanes 0..7's STGs and
        // partials reads before (b) lane 0's release atomic and before lane 0
        // can overwrite partials in the next iteration.
        if (warp == 0) {
            __syncwarp();
            if (lane == 0) {
                __threadfence();                    // release
                atomicAdd(&g_flags[t], 1u);
            }
        }
        // Other CTAs'/warps' next-iteration partial writes are gated by the
        // flag poll, so no second __syncthreads is needed.
    }
}

// ---------------------------------------------------------------------------
extern "C" void kernel_launch(void* const* d_in, const int* in_sizes, int n_in,
                              void* d_out, int out_size)
{
    const float* inp  = (const float*)d_in[0];  // [8192, 1024]
    const float* W_ih = (const float*)d_in[1];  // [3072, 1024]
    const float* W_hh = (const float*)d_in[2];  // [3072, 1024]
    const float* b_ih = (const float*)d_in[3];  // [3072]
    const float* b_hh = (const float*)d_in[4];  // [3072]
    float* out = (float*)d_out;                 // [8192, 1024]

    // 1) reset per-step flags (required for graph replay determinism)
    clear_flags_kernel<<<(S + 255) / 256, 256>>>();

    // 2) input-side projections: gx = inp @ W_ih^T + b_ih
    dim3 ggrid(3072 / 128, S / 128);
    gemm_gx_kernel<<<ggrid, 256>>>(inp, W_ih, b_ih);

    // 3) persistent sequential GRU scan (one wave of 128 CTAs)
    gru_scan_kernel<<<NSM, SCAN_THREADS>>>(W_hh, b_hh, out);
}

// round 2
// speedup vs baseline: 1.7610x; 1.7610x over previous
#include <cuda_runtime.h>
#include <cstdint>

#define S 8192
#define H 1024
#define NSM 128
#define SCAN_THREADS 512

// Scratch: input-side gate projections gx[S][3H] and per-step completion counters.
__device__ float g_gx[(size_t)S * 3 * H];
__device__ unsigned int g_flags[S];

// ---------------------------------------------------------------------------
// packed fp32x2 helpers (sm_103a FFMA2 path)
// ---------------------------------------------------------------------------
__device__ __forceinline__ unsigned long long pack2(float lo, float hi) {
    unsigned long long r;
    asm("mov.b64 %0, {%1, %2};" : "=l"(r) : "f"(lo), "f"(hi));
    return r;
}
__device__ __forceinline__ unsigned long long ffma2(unsigned long long a,
                                                    unsigned long long b,
                                                    unsigned long long c) {
    unsigned long long d;
    asm("fma.rn.f32x2 %0, %1, %2, %3;" : "=l"(d) : "l"(a), "l"(b), "l"(c));
    return d;
}
__device__ __forceinline__ float hsum2(unsigned long long a) {
    float lo, hi;
    asm("mov.b64 {%0, %1}, %2;" : "=f"(lo), "=f"(hi) : "l"(a));
    return lo + hi;
}

// ---------------------------------------------------------------------------
// Kernel 1: gx = inp @ W_ih^T + b_ih   (fp32 SIMT GEMM, 128x128x16 tiles)
// Also clears the per-step flag array (first 32 blocks) so each graph replay
// starts from a clean counter state.
// ---------------------------------------------------------------------------
__global__ __launch_bounds__(256) void gemm_gx_kernel(
    const float* __restrict__ A,
    const float* __restrict__ Wih,
    const float* __restrict__ bih)
{
    __shared__ float As[16][128 + 4];
    __shared__ float Bs[16][128 + 4];

    const int tid = threadIdx.x;
    const int flat_bid = blockIdx.y * gridDim.x + blockIdx.x;
    if (flat_bid < 32) g_flags[flat_bid * 256 + tid] = 0u;

    const int m0 = blockIdx.y * 128;
    const int n0 = blockIdx.x * 128;
    const int tx = tid & 15;
    const int ty = tid >> 4;

    float acc[8][8] = {};

    for (int kt = 0; kt < 1024; kt += 16) {
#pragma unroll
        for (int r = 0; r < 2; ++r) {
            int idx = tid + r * 256;
            int row = idx >> 2;
            int kq  = idx & 3;
            float4 v = *(const float4*)(A + (size_t)(m0 + row) * 1024 + kt + kq * 4);
            As[kq * 4 + 0][row] = v.x;
            As[kq * 4 + 1][row] = v.y;
            As[kq * 4 + 2][row] = v.z;
            As[kq * 4 + 3][row] = v.w;
        }
#pragma unroll
        for (int r = 0; r < 2; ++r) {
            int idx = tid + r * 256;
            int n  = idx >> 2;
            int kq = idx & 3;
            float4 v = *(const float4*)(Wih + (size_t)(n0 + n) * 1024 + kt + kq * 4);
            Bs[kq * 4 + 0][n] = v.x;
            Bs[kq * 4 + 1][n] = v.y;
            Bs[kq * 4 + 2][n] = v.z;
            Bs[kq * 4 + 3][n] = v.w;
        }
        __syncthreads();

#pragma unroll
        for (int k = 0; k < 16; ++k) {
            float ra[8], rb[8];
#pragma unroll
            for (int i = 0; i < 8; ++i) ra[i] = As[k][ty * 8 + i];
#pragma unroll
            for (int i = 0; i < 8; ++i) rb[i] = Bs[k][tx * 8 + i];
#pragma unroll
            for (int i = 0; i < 8; ++i)
#pragma unroll
                for (int j = 0; j < 8; ++j)
                    acc[i][j] = fmaf(ra[i], rb[j], acc[i][j]);
        }
        __syncthreads();
    }

#pragma unroll
    for (int i = 0; i < 8; ++i) {
        size_t rowoff = (size_t)(m0 + ty * 8 + i) * 3072 + n0 + tx * 8;
#pragma unroll
        for (int jq = 0; jq < 2; ++jq) {
            float4 v;
            v.x = acc[i][jq * 4 + 0] + bih[n0 + tx * 8 + jq * 4 + 0];
            v.y = acc[i][jq * 4 + 1] + bih[n0 + tx * 8 + jq * 4 + 1];
            v.z = acc[i][jq * 4 + 2] + bih[n0 + tx * 8 + jq * 4 + 2];
            v.w = acc[i][jq * 4 + 3] + bih[n0 + tx * 8 + jq * 4 + 3];
            *(float4*)(g_gx + rowoff + jq * 4) = v;
        }
    }
}

// ---------------------------------------------------------------------------
// Kernel 2: persistent GRU scan. 128 CTAs (one per SM, single wave),
// 512 threads each. Each CTA owns 8 output dims => 24 gate-rows of W_hh,
// held entirely in registers as packed f32x2 (FFMA2 path). h_t lives in
// d_out and is exchanged through L2; a per-step counter provides
// release/acquire sync. Only tid 0 polls (acquire) + __syncthreads fan-out.
//
// Thread layout: 16 warps = 4 k-chunks (256 cols each) x 4 row-groups
// (6 gate-rows each). Lane l owns 8 consecutive k within its chunk.
// ---------------------------------------------------------------------------
__global__ __launch_bounds__(SCAN_THREADS, 1) void gru_scan_kernel(
    const float* __restrict__ Whh,
    const float* __restrict__ bhh,
    float* __restrict__ out)
{
    const int tid  = threadIdx.x;
    const int warp = tid >> 5;
    const int lane = tid & 31;
    const int c = warp & 3;        // k-chunk id (0..3)
    const int g = warp >> 2;       // row-group id (0..3)
    const int obase = blockIdx.x * 8;
    const int k0 = c * 256 + lane * 8;

    // partials[c*8 + rep][gate-row], rep in 0..7 (lanes equal mod 8)
    __shared__ float partials[32][25];

    // --- preload 6 gate-rows x 8 cols of W_hh, packed as f32x2 pairs ---
    unsigned long long w2[6][4];
#pragma unroll
    for (int j = 0; j < 6; ++j) {
        int gr  = g * 6 + j;                          // 0..23
        int row = (gr >> 3) * H + obase + (gr & 7);   // gate*H + output index
        const float4* p = (const float4*)(Whh + (size_t)row * H + k0);
        float4 a = p[0], b = p[1];
        w2[j][0] = pack2(a.x, a.y);
        w2[j][1] = pack2(a.z, a.w);
        w2[j][2] = pack2(b.x, b.y);
        w2[j][3] = pack2(b.z, b.w);
    }

    const bool isw0 = (warp == 0);
    const int gate = lane >> 3;   // 0=r, 1=z, 2=n (for lanes < 24)
    const int o    = lane & 7;
    float bh = 0.f;
    if (isw0 && lane < 24) bh = bhh[gate * H + obase + o];
    float hprev = 0.f;            // lanes 0..7 carry h for their output dim

    const size_t gx_lane_off = (size_t)gate * H + obase + o;

    for (int t = 0; t < S; ++t) {
        // prefetch gx for this step (independent of the flag -> hides latency)
        float gxv = 0.f;
        if (isw0 && lane < 24)
            gxv = g_gx[(size_t)t * (3 * H) + gx_lane_off];

        unsigned long long h2[4];
        if (t == 0) {
#pragma unroll
            for (int q = 0; q < 4; ++q) h2[q] = 0ULL;
        } else {
            if (tid == 0) {
                const unsigned int* fp = &g_flags[t - 1];
                unsigned int v;
                do {
                    asm volatile("ld.acquire.gpu.global.u32 %0, [%1];"
                                 : "=r"(v) : "l"(fp) : "memory");
                } while (v < (unsigned)NSM);
            }
            __syncthreads();
            const float4* hp = (const float4*)(out + (size_t)(t - 1) * H + k0);
            float4 a = hp[0], b = hp[1];
            h2[0] = pack2(a.x, a.y);
            h2[1] = pack2(a.z, a.w);
            h2[2] = pack2(b.x, b.y);
            h2[3] = pack2(b.z, b.w);
        }

        // --- packed partial dots: 6 rows x 4 f32x2 FMAs ---
        float accv[6];
#pragma unroll
        for (int j = 0; j < 6; ++j) {
            unsigned long long acc = 0ULL;
#pragma unroll
            for (int q = 0; q < 4; ++q) acc = ffma2(w2[j][q], h2[q], acc);
            accv[j] = hsum2(acc);
        }

        // --- 2 shuffle rounds: reduce 32 lanes -> 8 representatives ---
#pragma unroll
        for (int j = 0; j < 6; ++j) {
            accv[j] += __shfl_xor_sync(0xFFFFFFFFu, accv[j], 16);
            accv[j] += __shfl_xor_sync(0xFFFFFFFFu, accv[j], 8);
        }
        if (lane < 8) {
#pragma unroll
            for (int j = 0; j < 6; ++j)
                partials[c * 8 + lane][g * 6 + j] = accv[j];
        }
        __syncthreads();

        // --- finalize: warp 0, one lane per gate-row (24 lanes) ---
        if (isw0) {
            float val = 0.f;
            if (lane < 24) {
                float s = bh;
#pragma unroll
                for (int q = 0; q < 32; ++q) s += partials[q][lane];
                // r/z rows: fold gx in now; n row: keep hidden side separate
                val = (gate < 2) ? (s + gxv) : s;
            }
            float v_z  = __shfl_sync(0xFFFFFFFFu, val, o + 8);
            float v_n  = __shfl_sync(0xFFFFFFFFu, val, o + 16);
            float gx_n = __shfl_sync(0xFFFFFFFFu, gxv, o + 16);
            if (lane < 8) {
                float r = 1.f / (1.f + __expf(-val));
                float z = 1.f / (1.f + __expf(-v_z));
                float n = tanhf(gx_n + r * v_n);
                float hn = z * (hprev - n) + n;   // (1-z)*n + z*h
                hprev = hn;
                out[(size_t)t * H + obase + o] = hn;
            }
            __syncwarp();
            if (lane == 0) {
                __threadfence();                  // release prior STGs
                atomicAdd(&g_flags[t], 1u);       // unused result -> RED
            }
        }
        // Non-finalizer warps are gated by the next step's flag poll +
        // __syncthreads, so partials are not overwritten early.
    }
}

// ---------------------------------------------------------------------------
extern "C" void kernel_launch(void* const* d_in, const int* in_sizes, int n_in,
                              void* d_out, int out_size)
{
    const float* inp  = (const float*)d_in[0];  // [8192, 1024]
    const float* W_ih = (const float*)d_in[1];  // [3072, 1024]
    const float* W_hh = (const float*)d_in[2];  // [3072, 1024]
    const float* b_ih = (const float*)d_in[3];  // [3072]
    const float* b_hh = (const float*)d_in[4];  // [3072]
    float* out = (float*)d_out;                 // [8192, 1024]

    // 1) gx = inp @ W_ih^T + b_ih (also clears g_flags for this replay)
    dim3 ggrid(3072 / 128, S / 128);
    gemm_gx_kernel<<<ggrid, 256>>>(inp, W_ih, b_ih);

    // 2) persistent sequential GRU scan (one wave of 128 CTAs)
    gru_scan_kernel<<<NSM, SCAN_THREADS>>>(W_hh, b_hh, out);
}